// round 5
// baseline (speedup 1.0000x reference)
#include <cuda_runtime.h>
#include <cuda_bf16.h>

// Fast Walsh-Hadamard transform, 16384 rows x 1024 fp32.
// y[row] = FWHT(x[row]) / 32, emitted as interleaved (real, 0) pairs.
//
// One warp per row, 32 values/thread, ZERO shuffles:
//   phase 1: thread owns contiguous [32l, 32l+32)  -> strides 1..16 in registers
//   one SW128-swizzled smem transpose (conflict-free both directions)
//   phase 2: thread owns {l + 32m}                 -> strides 32..512 in registers
// Loads: 8x float4 per thread. Stores: 32x STG.64, each warp-wavefront a
// contiguous 256B run (perfect coalescing, full sectors, zeros folded in).
// Warp-independent: only __syncwarp(), no block barriers.

#define DIMN 1024
#define WPB  4            // warps (=rows) per block -> 128 threads

__device__ __forceinline__ void bf(float &x, float &y) {
    float s = x + y;
    y = x - y;
    x = s;
}

// swizzle on 16-byte chunk index within a 4KB row: conflict-free for both
// per-thread-contiguous STS.128 and lane-strided LDS.32 (classic SW128).
__device__ __forceinline__ int swz(int c) { return c ^ ((c >> 3) & 7); }

__global__ void __launch_bounds__(32 * WPB, 8)
fwht_kernel(const float4* __restrict__ xin, float2* __restrict__ yout, int nrows)
{
    __shared__ float sm[WPB][DIMN];
    const int l   = threadIdx.x & 31;
    const int w   = threadIdx.x >> 5;
    const int row = blockIdx.x * WPB + w;
    if (row >= nrows) return;

    float v[32];

    // ---- load contiguous 128B per thread: 8 independent float4 ----
    const float4* in = xin + (size_t)row * (DIMN / 4) + 8 * l;
    #pragma unroll
    for (int i = 0; i < 8; i++) {
        float4 p = in[i];
        v[4*i+0] = p.x; v[4*i+1] = p.y; v[4*i+2] = p.z; v[4*i+3] = p.w;
    }

    // ---- phase 1: strides 1,2,4,8,16 (element = 32l + n) ----
    #pragma unroll
    for (int s = 1; s <= 16; s <<= 1) {
        #pragma unroll
        for (int n = 0; n < 32; n++)
            if (!(n & s)) bf(v[n], v[n + s]);
    }

    // ---- transpose out: 8 swizzled STS.128 (conflict-free) ----
    float* srow = sm[w];
    #pragma unroll
    for (int i = 0; i < 8; i++) {
        int cs = swz(8 * l + i);
        *reinterpret_cast<float4*>(srow + 4 * cs) =
            make_float4(v[4*i+0], v[4*i+1], v[4*i+2], v[4*i+3]);
    }
    __syncwarp();

    // ---- transpose in: thread now owns e = l + 32m; 32 LDS.32 (conflict-free) ----
    float u[32];
    #pragma unroll
    for (int m = 0; m < 32; m++) {
        int cs = swz(8 * m + (l >> 2));        // chunk of element l + 32m
        u[m] = srow[4 * cs + (l & 3)];
    }

    // ---- phase 2: strides 32,64,128,256,512 (bits of m) ----
    #pragma unroll
    for (int s = 1; s <= 16; s <<= 1) {
        #pragma unroll
        for (int m = 0; m < 32; m++)
            if (!(m & s)) bf(u[m], u[m + s]);
    }

    // ---- scaled (real, 0) stores: 32 STG.64, 256B contiguous per wavefront ----
    const float sc = 0.03125f;   // 1/sqrt(1024)
    float2* out = yout + (size_t)row * DIMN + l;
    #pragma unroll
    for (int m = 0; m < 32; m++) {
        __stcs(out + 32 * m, make_float2(u[m] * sc, 0.0f));
    }
}

extern "C" void kernel_launch(void* const* d_in, const int* in_sizes, int n_in,
                              void* d_out, int out_size)
{
    const float* x = (const float*)d_in[0];   // [B, S, 1024] fp32
    // d_in[1] is H; unused — the transform is computed directly.
    float* out = (float*)d_out;               // [B, S, 1024, 2] fp32

    const int nrows = in_sizes[0] / DIMN;     // 16384
    const int grid  = (nrows + WPB - 1) / WPB;

    fwht_kernel<<<grid, 32 * WPB>>>((const float4*)x, (float2*)out, nrows);
}

// round 6
// speedup vs baseline: 1.0101x; 1.0101x over previous
#include <cuda_runtime.h>
#include <cuda_bf16.h>

// Fast Walsh-Hadamard transform, 16384 rows x 1024 fp32.
// y[row] = FWHT(x[row]) / 32, emitted as interleaved (real, 0) pairs.
//
// One warp per row, 32 values/thread, ZERO shuffles:
//   phase 1: thread owns contiguous [32l, 32l+32)  -> strides 1..16 in registers
//   one SW128-swizzled smem transpose (conflict-free both directions)
//   phase 2: thread owns {l + 32m}                 -> strides 32..512 in registers
// Loads: 8x float4 per thread. Stores: 32x STG.64, each warp-wavefront a
// contiguous 256B run (perfect coalescing, full sectors, zeros folded in).
// Warp-independent: only __syncwarp(), no block barriers.

#define DIMN 1024
#define WPB  4            // warps (=rows) per block -> 128 threads

__device__ __forceinline__ void bf(float &x, float &y) {
    float s = x + y;
    y = x - y;
    x = s;
}

// swizzle on 16-byte chunk index within a 4KB row: conflict-free for both
// per-thread-contiguous STS.128 and lane-strided LDS.32 (classic SW128).
__device__ __forceinline__ int swz(int c) { return c ^ ((c >> 3) & 7); }

__global__ void __launch_bounds__(32 * WPB, 8)
fwht_kernel(const float4* __restrict__ xin, float2* __restrict__ yout, int nrows)
{
    __shared__ float sm[WPB][DIMN];
    const int l   = threadIdx.x & 31;
    const int w   = threadIdx.x >> 5;
    const int row = blockIdx.x * WPB + w;
    if (row >= nrows) return;

    float v[32];

    // ---- load contiguous 128B per thread: 8 independent float4 ----
    const float4* in = xin + (size_t)row * (DIMN / 4) + 8 * l;
    #pragma unroll
    for (int i = 0; i < 8; i++) {
        float4 p = in[i];
        v[4*i+0] = p.x; v[4*i+1] = p.y; v[4*i+2] = p.z; v[4*i+3] = p.w;
    }

    // ---- phase 1: strides 1,2,4,8,16 (element = 32l + n) ----
    #pragma unroll
    for (int s = 1; s <= 16; s <<= 1) {
        #pragma unroll
        for (int n = 0; n < 32; n++)
            if (!(n & s)) bf(v[n], v[n + s]);
    }

    // ---- transpose out: 8 swizzled STS.128 (conflict-free) ----
    float* srow = sm[w];
    #pragma unroll
    for (int i = 0; i < 8; i++) {
        int cs = swz(8 * l + i);
        *reinterpret_cast<float4*>(srow + 4 * cs) =
            make_float4(v[4*i+0], v[4*i+1], v[4*i+2], v[4*i+3]);
    }
    __syncwarp();

    // ---- transpose in: thread now owns e = l + 32m; 32 LDS.32 (conflict-free) ----
    float u[32];
    #pragma unroll
    for (int m = 0; m < 32; m++) {
        int cs = swz(8 * m + (l >> 2));        // chunk of element l + 32m
        u[m] = srow[4 * cs + (l & 3)];
    }

    // ---- phase 2: strides 32,64,128,256,512 (bits of m) ----
    #pragma unroll
    for (int s = 1; s <= 16; s <<= 1) {
        #pragma unroll
        for (int m = 0; m < 32; m++)
            if (!(m & s)) bf(u[m], u[m + s]);
    }

    // ---- scaled (real, 0) stores: 32 STG.64, 256B contiguous per wavefront ----
    const float sc = 0.03125f;   // 1/sqrt(1024)
    float2* out = yout + (size_t)row * DIMN + l;
    #pragma unroll
    for (int m = 0; m < 32; m++) {
        __stcs(out + 32 * m, make_float2(u[m] * sc, 0.0f));
    }
}

extern "C" void kernel_launch(void* const* d_in, const int* in_sizes, int n_in,
                              void* d_out, int out_size)
{
    const float* x = (const float*)d_in[0];   // [B, S, 1024] fp32
    // d_in[1] is H; unused — the transform is computed directly.
    float* out = (float*)d_out;               // [B, S, 1024, 2] fp32

    const int nrows = in_sizes[0] / DIMN;     // 16384
    const int grid  = (nrows + WPB - 1) / WPB;

    fwht_kernel<<<grid, 32 * WPB>>>((const float4*)x, (float2*)out, nrows);
}

// round 7
// speedup vs baseline: 1.0152x; 1.0051x over previous
#include <cuda_runtime.h>
#include <cuda_bf16.h>

// Fast Walsh-Hadamard transform, 16384 rows x 1024 fp32.
// y[row] = FWHT(x[row]) / 32, emitted as interleaved (real, 0) pairs.
//
// One warp per row, 32 values/thread, ZERO shuffles:
//   phase 1: thread owns contiguous [32l, 32l+32)  -> strides 1..16 in registers
//   one SW128-swizzled smem transpose (conflict-free both directions)
//   phase 2: thread owns {l + 32m}                 -> strides 32..512 in registers
// Loads: 8x float4 per thread. Stores: 32x STG.64, each warp-wavefront a
// contiguous 256B run (perfect coalescing, full sectors, zeros folded in).
// Warp-independent: only __syncwarp(), no block barriers.

#define DIMN 1024
#define WPB  4            // warps (=rows) per block -> 128 threads

__device__ __forceinline__ void bf(float &x, float &y) {
    float s = x + y;
    y = x - y;
    x = s;
}

// swizzle on 16-byte chunk index within a 4KB row: conflict-free for both
// per-thread-contiguous STS.128 and lane-strided LDS.32 (classic SW128).
__device__ __forceinline__ int swz(int c) { return c ^ ((c >> 3) & 7); }

__global__ void __launch_bounds__(32 * WPB, 8)
fwht_kernel(const float4* __restrict__ xin, float2* __restrict__ yout, int nrows)
{
    __shared__ float sm[WPB][DIMN];
    const int l   = threadIdx.x & 31;
    const int w   = threadIdx.x >> 5;
    const int row = blockIdx.x * WPB + w;
    if (row >= nrows) return;

    float v[32];

    // ---- load contiguous 128B per thread: 8 independent float4 ----
    const float4* in = xin + (size_t)row * (DIMN / 4) + 8 * l;
    #pragma unroll
    for (int i = 0; i < 8; i++) {
        float4 p = in[i];
        v[4*i+0] = p.x; v[4*i+1] = p.y; v[4*i+2] = p.z; v[4*i+3] = p.w;
    }

    // ---- phase 1: strides 1,2,4,8,16 (element = 32l + n) ----
    #pragma unroll
    for (int s = 1; s <= 16; s <<= 1) {
        #pragma unroll
        for (int n = 0; n < 32; n++)
            if (!(n & s)) bf(v[n], v[n + s]);
    }

    // ---- transpose out: 8 swizzled STS.128 (conflict-free) ----
    float* srow = sm[w];
    #pragma unroll
    for (int i = 0; i < 8; i++) {
        int cs = swz(8 * l + i);
        *reinterpret_cast<float4*>(srow + 4 * cs) =
            make_float4(v[4*i+0], v[4*i+1], v[4*i+2], v[4*i+3]);
    }
    __syncwarp();

    // ---- transpose in: thread now owns e = l + 32m; 32 LDS.32 (conflict-free) ----
    float u[32];
    #pragma unroll
    for (int m = 0; m < 32; m++) {
        int cs = swz(8 * m + (l >> 2));        // chunk of element l + 32m
        u[m] = srow[4 * cs + (l & 3)];
    }

    // ---- phase 2: strides 32,64,128,256,512 (bits of m) ----
    #pragma unroll
    for (int s = 1; s <= 16; s <<= 1) {
        #pragma unroll
        for (int m = 0; m < 32; m++)
            if (!(m & s)) bf(u[m], u[m + s]);
    }

    // ---- scaled (real, 0) stores: 32 STG.64, 256B contiguous per wavefront ----
    const float sc = 0.03125f;   // 1/sqrt(1024)
    float2* out = yout + (size_t)row * DIMN + l;
    #pragma unroll
    for (int m = 0; m < 32; m++) {
        __stcs(out + 32 * m, make_float2(u[m] * sc, 0.0f));
    }
}

extern "C" void kernel_launch(void* const* d_in, const int* in_sizes, int n_in,
                              void* d_out, int out_size)
{
    const float* x = (const float*)d_in[0];   // [B, S, 1024] fp32
    // d_in[1] is H; unused — the transform is computed directly.
    float* out = (float*)d_out;               // [B, S, 1024, 2] fp32

    const int nrows = in_sizes[0] / DIMN;     // 16384
    const int grid  = (nrows + WPB - 1) / WPB;

    fwht_kernel<<<grid, 32 * WPB>>>((const float4*)x, (float2*)out, nrows);
}